// round 1
// baseline (speedup 1.0000x reference)
#include <cuda_runtime.h>

// OBMC: 5 bilinear backward warps of x[4,64,256,256] by flow and 4 integer-shifted
// flows, concatenated along channels -> out[4,320,256,256] (fp32).
//
// Key facts exploited:
//  * _shift(flow, bias) with integer bias is exactly a zero-padded integer shift
//    of the flow field (bilinear weights collapse to {1,0,0,0}).
//  * Bilinear tap weights/indices depend only on (b, g, y, x) -> compute once,
//    reuse across all 64 channels.
//
// One thread = one output x position for one (b, g, y). Inner loop over c.
// Stores coalesced along W; gathers hit L1/L2 (flow std ~4 px locality).

#define BB 4
#define CC 64
#define HH 256
#define WW 256
#define HW (HH * WW)

__global__ __launch_bounds__(256, 8)
void obmc_kernel(const float* __restrict__ x,
                 const float* __restrict__ flow,
                 float* __restrict__ out) {
    const int xp = threadIdx.x;           // 0..255 (W == blockDim.x)
    const int y  = blockIdx.y;            // 0..255
    const int bg = blockIdx.z;            // 0..19
    const int b  = bg / 5;
    const int g  = bg % 5;

    // --- fetch (possibly shifted) flow for this pixel ---
    const float* fb = flow + (size_t)b * 2 * HW;
    float fx, fy;
    if (g == 0) {
        fx = fb[y * WW + xp];
        fy = fb[HW + y * WW + xp];
    } else {
        // bias order: g1=[0,1] -> (sx=0,sy=1); g2=[1,0] -> (1,0);
        //             g3=[0,-1] -> (0,-1);    g4=[-1,0] -> (-1,0)
        const int sx = (g == 2) - (g == 4);
        const int sy = (g == 1) - (g == 3);
        const int xs = xp + sx;
        const int ys = y + sy;
        if (xs >= 0 && xs < WW && ys >= 0 && ys < HH) {
            fx = fb[ys * WW + xs];
            fy = fb[HW + ys * WW + xs];
        } else {
            fx = 0.0f;  // zero-padded shift -> zero flow -> identity sample
            fy = 0.0f;
        }
    }

    // --- bilinear setup (channel-invariant) ---
    const float gx = (float)xp + fx;
    const float gy = (float)y  + fy;
    const float x0f = floorf(gx);
    const float y0f = floorf(gy);
    const float wx = gx - x0f;
    const float wy = gy - y0f;
    const int x0 = (int)x0f, y0 = (int)y0f;
    const int x1 = x0 + 1,   y1 = y0 + 1;

    const bool vx0 = (x0 >= 0) & (x0 < WW);
    const bool vx1 = (x1 >= 0) & (x1 < WW);
    const bool vy0 = (y0 >= 0) & (y0 < HH);
    const bool vy1 = (y1 >= 0) & (y1 < HH);

    const float w00 = (1.0f - wx) * (1.0f - wy) * (float)(vx0 & vy0);
    const float w01 = wx * (1.0f - wy)          * (float)(vx1 & vy0);
    const float w10 = (1.0f - wx) * wy          * (float)(vx0 & vy1);
    const float w11 = wx * wy                   * (float)(vx1 & vy1);

    const int cx0 = min(max(x0, 0), WW - 1);
    const int cx1 = min(max(x1, 0), WW - 1);
    const int cy0 = min(max(y0, 0), HH - 1);
    const int cy1 = min(max(y1, 0), HH - 1);

    const int i00 = cy0 * WW + cx0;
    const int i01 = cy0 * WW + cx1;
    const int i10 = cy1 * WW + cx0;
    const int i11 = cy1 * WW + cx1;

    const float* __restrict__ xb = x + (size_t)b * CC * HW;
    float* __restrict__ ob = out + ((size_t)(b * 5 + g) * CC) * HW
                                 + (size_t)y * WW + xp;

    // --- apply to all channels; unroll for MLP ---
    #pragma unroll 8
    for (int c = 0; c < CC; ++c) {
        const float* __restrict__ p = xb + (size_t)c * HW;
        float v = w00 * __ldg(p + i00);
        v = fmaf(w01, __ldg(p + i01), v);
        v = fmaf(w10, __ldg(p + i10), v);
        v = fmaf(w11, __ldg(p + i11), v);
        ob[(size_t)c * HW] = v;
    }
}

extern "C" void kernel_launch(void* const* d_in, const int* in_sizes, int n_in,
                              void* d_out, int out_size) {
    const float* x    = (const float*)d_in[0];
    const float* flow = (const float*)d_in[1];
    float* out        = (float*)d_out;

    dim3 grid(1, HH, BB * 5);   // 5120 blocks
    dim3 block(WW);             // 256 threads, one per x
    obmc_kernel<<<grid, block>>>(x, flow, out);
}

// round 2
// speedup vs baseline: 1.9041x; 1.9041x over previous
#include <cuda_runtime.h>

// OBMC fused: one thread per flow pixel produces all 5 group outputs.
//
// Derivation: group g's output at (yo,xo) samples x at (xo+fx, yo+fy) where
// (fx,fy) is the flow at the shifted position. Inverting: flow pixel (Y,X)
// feeds g0@(Y,X), g1@(Y-1,X), g3@(Y+1,X), g2@(Y,X-1), g4@(Y,X+1), all with
// the SAME fractional weights (wx,wy); tap coords are rows {y0-1,y0,y1,y1+1}
// x cols {x0-1,x0,x1,x1+1}. Union of the 5x4 tap-uses = 12 distinct loads
// (vs 20 in the unfused version) -> 40% less L1/L2 gather traffic.
//
// Uncovered borders (shift reads OOB flow -> zero flow -> identity sample):
//   g1 row 255, g3 row 0, g2 col 255, g4 col 0  are copies of x.

#define BB 4
#define CC 64
#define HH 256
#define WW 256
#define HW (HH * WW)

__global__ __launch_bounds__(256, 3)
void obmc_fused_kernel(const float* __restrict__ x,
                       const float* __restrict__ flow,
                       float* __restrict__ out) {
    const int xp = threadIdx.x;            // 0..255
    const int Y  = blockIdx.x;             // 0..255
    const int b  = blockIdx.y;             // 0..3

    const int pix = Y * WW + xp;
    const float* fb = flow + (size_t)b * 2 * HW;
    const float fx = fb[pix];
    const float fy = fb[HW + pix];

    const float gx = (float)xp + fx;
    const float gy = (float)Y  + fy;
    const float x0f = floorf(gx);
    const float y0f = floorf(gy);
    const float wx = gx - x0f;
    const float wy = gy - y0f;
    const int x0 = (int)x0f;
    const int y0 = (int)y0f;

    // rows r0..r3 = y0-1..y0+2, cols c0..c3 = x0-1..x0+2 (clamped + validity)
    int rofs[4], cofs[4];
    float vr[4], vc[4];
    #pragma unroll
    for (int i = 0; i < 4; ++i) {
        const int r = y0 - 1 + i;
        vr[i] = (r >= 0 && r < HH) ? 1.0f : 0.0f;
        rofs[i] = min(max(r, 0), HH - 1) * WW;
        const int c = x0 - 1 + i;
        vc[i] = (c >= 0 && c < WW) ? 1.0f : 0.0f;
        cofs[i] = min(max(c, 0), WW - 1);
    }

    const float w00 = (1.0f - wx) * (1.0f - wy);
    const float w01 = wx * (1.0f - wy);
    const float w10 = (1.0f - wx) * wy;
    const float w11 = wx * wy;

    // Per-group masked weights (taps: rows rA,rB x cols cA,cB per group)
    const float g0w0 = w00 * vr[1] * vc[1], g0w1 = w01 * vr[1] * vc[2];
    const float g0w2 = w10 * vr[2] * vc[1], g0w3 = w11 * vr[2] * vc[2];

    const float g1w0 = w00 * vr[0] * vc[1], g1w1 = w01 * vr[0] * vc[2];
    const float g1w2 = w10 * vr[1] * vc[1], g1w3 = w11 * vr[1] * vc[2];

    const float g3w0 = w00 * vr[2] * vc[1], g3w1 = w01 * vr[2] * vc[2];
    const float g3w2 = w10 * vr[3] * vc[1], g3w3 = w11 * vr[3] * vc[2];

    const float g2w0 = w00 * vr[1] * vc[0], g2w1 = w01 * vr[1] * vc[1];
    const float g2w2 = w10 * vr[2] * vc[0], g2w3 = w11 * vr[2] * vc[1];

    const float g4w0 = w00 * vr[1] * vc[2], g4w1 = w01 * vr[1] * vc[3];
    const float g4w2 = w10 * vr[2] * vc[2], g4w3 = w11 * vr[2] * vc[3];

    // 12 distinct tap offsets
    const int o_r1c0 = rofs[1] + cofs[0], o_r1c1 = rofs[1] + cofs[1];
    const int o_r1c2 = rofs[1] + cofs[2], o_r1c3 = rofs[1] + cofs[3];
    const int o_r2c0 = rofs[2] + cofs[0], o_r2c1 = rofs[2] + cofs[1];
    const int o_r2c2 = rofs[2] + cofs[2], o_r2c3 = rofs[2] + cofs[3];
    const int o_r0c1 = rofs[0] + cofs[1], o_r0c2 = rofs[0] + cofs[2];
    const int o_r3c1 = rofs[3] + cofs[1], o_r3c2 = rofs[3] + cofs[2];

    const float* __restrict__ xb = x + (size_t)b * CC * HW;
    const size_t obase = (size_t)b * 5 * CC * HW + (size_t)pix;

    float* p0 = out + obase;                               // g0 @ (Y, xp)
    float* p1 = out + obase + (size_t)1 * CC * HW - WW;    // g1 @ (Y-1, xp)
    float* p2 = out + obase + (size_t)2 * CC * HW - 1;     // g2 @ (Y, xp-1)
    float* p3 = out + obase + (size_t)3 * CC * HW + WW;    // g3 @ (Y+1, xp)
    float* p4 = out + obase + (size_t)4 * CC * HW + 1;     // g4 @ (Y, xp+1)

    const bool s1 = (Y  >= 1),      s3 = (Y  <= HH - 2);
    const bool s2 = (xp >= 1),      s4 = (xp <= WW - 2);
    const bool e1 = (Y == HH - 1),  e3 = (Y == 0);
    const bool e2 = (xp == WW - 1), e4 = (xp == 0);
    const bool eany = e1 | e2 | e3 | e4;

    const float* __restrict__ p = xb;
    #pragma unroll 4
    for (int c = 0; c < CC; ++c) {
        const float t_r1c0 = __ldg(p + o_r1c0);
        const float t_r1c1 = __ldg(p + o_r1c1);
        const float t_r1c2 = __ldg(p + o_r1c2);
        const float t_r1c3 = __ldg(p + o_r1c3);
        const float t_r2c0 = __ldg(p + o_r2c0);
        const float t_r2c1 = __ldg(p + o_r2c1);
        const float t_r2c2 = __ldg(p + o_r2c2);
        const float t_r2c3 = __ldg(p + o_r2c3);
        const float t_r0c1 = __ldg(p + o_r0c1);
        const float t_r0c2 = __ldg(p + o_r0c2);
        const float t_r3c1 = __ldg(p + o_r3c1);
        const float t_r3c2 = __ldg(p + o_r3c2);

        float v0 = g0w0 * t_r1c1;
        v0 = fmaf(g0w1, t_r1c2, v0); v0 = fmaf(g0w2, t_r2c1, v0); v0 = fmaf(g0w3, t_r2c2, v0);
        float v1 = g1w0 * t_r0c1;
        v1 = fmaf(g1w1, t_r0c2, v1); v1 = fmaf(g1w2, t_r1c1, v1); v1 = fmaf(g1w3, t_r1c2, v1);
        float v3 = g3w0 * t_r2c1;
        v3 = fmaf(g3w1, t_r2c2, v3); v3 = fmaf(g3w2, t_r3c1, v3); v3 = fmaf(g3w3, t_r3c2, v3);
        float v2 = g2w0 * t_r1c0;
        v2 = fmaf(g2w1, t_r1c1, v2); v2 = fmaf(g2w2, t_r2c0, v2); v2 = fmaf(g2w3, t_r2c1, v2);
        float v4 = g4w0 * t_r1c2;
        v4 = fmaf(g4w1, t_r1c3, v4); v4 = fmaf(g4w2, t_r2c2, v4); v4 = fmaf(g4w3, t_r2c3, v4);

        __stcs(p0, v0);
        if (s1) __stcs(p1, v1);
        if (s2) __stcs(p2, v2);
        if (s3) __stcs(p3, v3);
        if (s4) __stcs(p4, v4);

        if (eany) {  // rare: identity-copy borders (zero shifted flow)
            const float xv = __ldg(p + pix);
            const size_t cb = obase + (size_t)c * HW;
            if (e1) __stcs(out + cb + (size_t)1 * CC * HW, xv);           // g1 row 255
            if (e3) __stcs(out + cb + (size_t)3 * CC * HW, xv);           // g3 row 0
            if (e2) __stcs(out + cb + (size_t)2 * CC * HW, xv);           // g2 col 255
            if (e4) __stcs(out + cb + (size_t)4 * CC * HW, xv);           // g4 col 0
        }

        p  += HW;
        p0 += HW; p1 += HW; p2 += HW; p3 += HW; p4 += HW;
    }
}

extern "C" void kernel_launch(void* const* d_in, const int* in_sizes, int n_in,
                              void* d_out, int out_size) {
    const float* x    = (const float*)d_in[0];
    const float* flow = (const float*)d_in[1];
    float* out        = (float*)d_out;

    dim3 grid(HH, BB);     // 1024 blocks: one row per block per batch
    dim3 block(WW);        // 256 threads, one per flow pixel
    obmc_fused_kernel<<<grid, block>>>(x, flow, out);
}

// round 3
// speedup vs baseline: 1.9092x; 1.0027x over previous
#include <cuda_runtime.h>

// OBMC, smem-tiled: stage a zero-padded per-channel row window in shared
// memory with coalesced float4 loads; serve all 12 bilinear taps (5 fused
// output groups per flow pixel, cf. R2 derivation) from LDS.
//
// Zero-padding (zero row + zero col pads) replaces validity masking: invalid
// taps read stored zeros, so inner loop weights are the unmasked bilinear
// weights. Pixels whose valid taps fall outside the staged window (|fy|>12,
// ~0.27%) take the exact global-gather fallback path.

#define BB 4
#define CC 64
#define HH 256
#define WW 256
#define HW (HH * WW)

#define TILE_H 4
#define FMAX 12
#define WROWS 32               // 2*FMAX + 8
#define WSTRIDE 264            // 4 zero cols | 256 data | 4 zero cols
#define ZROW 32                // dedicated all-zero row
#define WSIZE ((WROWS + 1) * WSTRIDE)
#define CPB 32                 // channels per block
#define NCG (CC / CPB)

__global__ __launch_bounds__(256, 2)
void obmc_tiled(const float* __restrict__ x,
                const float* __restrict__ flow,
                float* __restrict__ out)
{
    __shared__ float win[2][WSIZE];

    const int tid = threadIdx.x;                 // output col
    const int Y0  = blockIdx.x * TILE_H;
    const int b   = blockIdx.y;
    const int c0  = blockIdx.z * CPB;
    const int winLo = Y0 - (FMAX + 2);

    // ---- one-time pads: zero row + zero col pads in both buffers ----
    for (int i = tid; i < WSTRIDE; i += 256) {
        win[0][ZROW * WSTRIDE + i] = 0.f;
        win[1][ZROW * WSTRIDE + i] = 0.f;
    }
    for (int i = tid; i < WROWS * 8; i += 256) {
        const int r = i >> 3, k = i & 7;
        const int col = (k < 4) ? k : (256 + k);  // 0..3 and 260..263
        win[0][r * WSTRIDE + col] = 0.f;
        win[1][r * WSTRIDE + col] = 0.f;
    }

    // ---- per-pixel params (channel-invariant), kept in registers ----
    float w00[TILE_H], w01[TILE_H], w10[TILE_H], w11[TILE_H];
    unsigned po[TILE_H][6];     // 12 uint16 smem offsets, packed
    unsigned offC[TILE_H];      // center value offset (border copies)
    unsigned fbmask = 0;

    const float* fl = flow + (size_t)b * 2 * HW;
    #pragma unroll
    for (int t = 0; t < TILE_H; ++t) {
        const int Yo = Y0 + t;
        const int pix = Yo * WW + tid;
        const float fx = fl[pix];
        const float fy = fl[HW + pix];
        const float gx = (float)tid + fx;
        const float gy = (float)Yo  + fy;
        const float x0f = floorf(gx), y0f = floorf(gy);
        const float wx = gx - x0f,    wy = gy - y0f;
        const int x0 = (int)x0f, y0 = (int)y0f;
        w00[t] = (1.f - wx) * (1.f - wy);
        w01[t] = wx * (1.f - wy);
        w10[t] = (1.f - wx) * wy;
        w11[t] = wx * wy;

        int srow[4];
        bool fb = false;
        #pragma unroll
        for (int i = 0; i < 4; ++i) {
            const int r = y0 - 1 + i;
            if (r >= 0 && r < HH) {
                const int s = r - winLo;
                if (s < 0 || s >= WROWS) fb = true;
                srow[i] = min(max(s, 0), WROWS - 1);
            } else {
                srow[i] = ZROW;                  // reads zero
            }
        }
        int scol[4];
        #pragma unroll
        for (int j = 0; j < 4; ++j)
            scol[j] = min(max(x0 - 1 + j + 4, 0), WSTRIDE - 1);  // pads are zero

        #define OFS(i, j) ((unsigned)(srow[i] * WSTRIDE + scol[j]))
        po[t][0] = OFS(1,0) | (OFS(1,1) << 16);
        po[t][1] = OFS(1,2) | (OFS(1,3) << 16);
        po[t][2] = OFS(2,0) | (OFS(2,1) << 16);
        po[t][3] = OFS(2,2) | (OFS(2,3) << 16);
        po[t][4] = OFS(0,1) | (OFS(0,2) << 16);
        po[t][5] = OFS(3,1) | (OFS(3,2) << 16);
        #undef OFS
        offC[t] = (unsigned)((Yo - winLo) * WSTRIDE + tid + 4);
        if (fb) fbmask |= 1u << t;
    }

    const float* xg = x + ((size_t)b * CC + c0) * HW;

    // ---- stage channel 0 into buffer 0 ----
    #pragma unroll
    for (int k = 0; k < 8; ++k) {
        const int idx = tid + k * 256;           // WROWS*64 = 2048 float4s
        const int row = idx >> 6, c4 = (idx & 63) << 2;
        const int sr = winLo + row;
        float4 v = make_float4(0.f, 0.f, 0.f, 0.f);
        if (sr >= 0 && sr < HH) v = *(const float4*)(xg + (size_t)sr * WW + c4);
        *(float4*)&win[0][row * WSTRIDE + 4 + c4] = v;
    }
    __syncthreads();

    int cur = 0;
    for (int c = 0; c < CPB; ++c) {
        // prefetch next channel's window into registers (latency overlaps compute)
        float4 st[8];
        const bool more = (c + 1 < CPB);
        if (more) {
            const float* plane = xg + (size_t)(c + 1) * HW;
            #pragma unroll
            for (int k = 0; k < 8; ++k) {
                const int idx = tid + k * 256;
                const int row = idx >> 6, c4 = (idx & 63) << 2;
                const int sr = winLo + row;
                st[k] = make_float4(0.f, 0.f, 0.f, 0.f);
                if (sr >= 0 && sr < HH)
                    st[k] = *(const float4*)(plane + (size_t)sr * WW + c4);
            }
        }

        // ---- compute channel c from win[cur] ----
        const float* __restrict__ buf = win[cur];
        const int cch = c0 + c;
        #pragma unroll
        for (int t = 0; t < TILE_H; ++t) {
            const int Yo = Y0 + t;
            const int pix = Yo * WW + tid;
            float v0, v1, v2, v3, v4;

            if (fbmask & (1u << t)) {
                // rare exact global fallback (R2 path)
                const float fx = fl[pix], fy = fl[HW + pix];
                const float gx = (float)tid + fx, gy = (float)Yo + fy;
                const float x0f = floorf(gx), y0f = floorf(gy);
                const float wx = gx - x0f, wy = gy - y0f;
                const int x0 = (int)x0f, y0 = (int)y0f;
                int rofs[4], cofs[4]; float vr[4], vc[4];
                #pragma unroll
                for (int i = 0; i < 4; ++i) {
                    const int r = y0 - 1 + i;
                    vr[i] = (r >= 0 && r < HH) ? 1.f : 0.f;
                    rofs[i] = min(max(r, 0), HH - 1) * WW;
                    const int cI = x0 - 1 + i;
                    vc[i] = (cI >= 0 && cI < WW) ? 1.f : 0.f;
                    cofs[i] = min(max(cI, 0), WW - 1);
                }
                const float b00 = (1.f-wx)*(1.f-wy), b01 = wx*(1.f-wy);
                const float b10 = (1.f-wx)*wy,       b11 = wx*wy;
                const float* p = x + ((size_t)b * CC + cch) * HW;
                const float t10 = __ldg(p + rofs[1] + cofs[0]) * vr[1] * vc[0];
                const float t11 = __ldg(p + rofs[1] + cofs[1]) * vr[1] * vc[1];
                const float t12 = __ldg(p + rofs[1] + cofs[2]) * vr[1] * vc[2];
                const float t13 = __ldg(p + rofs[1] + cofs[3]) * vr[1] * vc[3];
                const float t20 = __ldg(p + rofs[2] + cofs[0]) * vr[2] * vc[0];
                const float t21 = __ldg(p + rofs[2] + cofs[1]) * vr[2] * vc[1];
                const float t22 = __ldg(p + rofs[2] + cofs[2]) * vr[2] * vc[2];
                const float t23 = __ldg(p + rofs[2] + cofs[3]) * vr[2] * vc[3];
                const float t01 = __ldg(p + rofs[0] + cofs[1]) * vr[0] * vc[1];
                const float t02 = __ldg(p + rofs[0] + cofs[2]) * vr[0] * vc[2];
                const float t31 = __ldg(p + rofs[3] + cofs[1]) * vr[3] * vc[1];
                const float t32 = __ldg(p + rofs[3] + cofs[2]) * vr[3] * vc[2];
                v0 = fmaf(b11,t22, fmaf(b10,t21, fmaf(b01,t12, b00*t11)));
                v1 = fmaf(b11,t12, fmaf(b10,t11, fmaf(b01,t02, b00*t01)));
                v3 = fmaf(b11,t32, fmaf(b10,t31, fmaf(b01,t22, b00*t21)));
                v2 = fmaf(b11,t21, fmaf(b10,t20, fmaf(b01,t11, b00*t10)));
                v4 = fmaf(b11,t23, fmaf(b10,t22, fmaf(b01,t13, b00*t12)));
            } else {
                const float t10 = buf[po[t][0] & 0xFFFFu];
                const float t11 = buf[po[t][0] >> 16];
                const float t12 = buf[po[t][1] & 0xFFFFu];
                const float t13 = buf[po[t][1] >> 16];
                const float t20 = buf[po[t][2] & 0xFFFFu];
                const float t21 = buf[po[t][2] >> 16];
                const float t22 = buf[po[t][3] & 0xFFFFu];
                const float t23 = buf[po[t][3] >> 16];
                const float t01 = buf[po[t][4] & 0xFFFFu];
                const float t02 = buf[po[t][4] >> 16];
                const float t31 = buf[po[t][5] & 0xFFFFu];
                const float t32 = buf[po[t][5] >> 16];
                v0 = fmaf(w11[t],t22, fmaf(w10[t],t21, fmaf(w01[t],t12, w00[t]*t11)));
                v1 = fmaf(w11[t],t12, fmaf(w10[t],t11, fmaf(w01[t],t02, w00[t]*t01)));
                v3 = fmaf(w11[t],t32, fmaf(w10[t],t31, fmaf(w01[t],t22, w00[t]*t21)));
                v2 = fmaf(w11[t],t21, fmaf(w10[t],t20, fmaf(w01[t],t11, w00[t]*t10)));
                v4 = fmaf(w11[t],t23, fmaf(w10[t],t22, fmaf(w01[t],t13, w00[t]*t12)));
            }

            const size_t gbase = ((size_t)(b * 5) * CC + cch) * HW + (size_t)pix;
            __stcs(out + gbase, v0);                                        // g0 @ (Yo, xp)
            if (Yo  >= 1)      __stcs(out + gbase + (size_t)1*CC*HW - WW, v1);
            if (tid >= 1)      __stcs(out + gbase + (size_t)2*CC*HW - 1,  v2);
            if (Yo  <= HH - 2) __stcs(out + gbase + (size_t)3*CC*HW + WW, v3);
            if (tid <= WW - 2) __stcs(out + gbase + (size_t)4*CC*HW + 1,  v4);

            if ((Yo == HH - 1) | (Yo == 0) | (tid == WW - 1) | (tid == 0)) {
                const float xv = buf[offC[t]];    // identity copy (zero shifted flow)
                if (Yo == HH - 1)  __stcs(out + gbase + (size_t)1*CC*HW, xv);
                if (Yo == 0)       __stcs(out + gbase + (size_t)3*CC*HW, xv);
                if (tid == WW - 1) __stcs(out + gbase + (size_t)2*CC*HW, xv);
                if (tid == 0)      __stcs(out + gbase + (size_t)4*CC*HW, xv);
            }
        }

        if (more) {
            float* nb = win[cur ^ 1];
            #pragma unroll
            for (int k = 0; k < 8; ++k) {
                const int idx = tid + k * 256;
                const int row = idx >> 6, c4 = (idx & 63) << 2;
                *(float4*)&nb[row * WSTRIDE + 4 + c4] = st[k];
            }
        }
        __syncthreads();
        cur ^= 1;
    }
}

extern "C" void kernel_launch(void* const* d_in, const int* in_sizes, int n_in,
                              void* d_out, int out_size) {
    const float* x    = (const float*)d_in[0];
    const float* flow = (const float*)d_in[1];
    float* out        = (float*)d_out;

    dim3 grid(HH / TILE_H, BB, NCG);   // 64 x 4 x 2 = 512 blocks
    dim3 block(256);
    obmc_tiled<<<grid, block>>>(x, flow, out);
}